// round 5
// baseline (speedup 1.0000x reference)
#include <cuda_runtime.h>
#include <math.h>

#define H 4096

// Scratch: 9 [3,H] mv outputs + hR[2,H] + 7 [H] vectors = 36*H floats.
__device__ float g_scratch[36 * H];

struct P {
    const float* L; const float* R;
    const float* x; const float* hp;
    const float* b; const float* Wsc;
    float* xL; float* hL; float* hR;          // hR: l=0..1 only
    float* Rr; float* Rz1;
    float* Rrh; float* RoneMZ; float* Rz2h;
    float* Lht; float* Lzh;
    float* r; float* z1; float* rh; float* oneMZ; float* z2h;
    float* htilde; float* zhtil;
    float* out;
};

// ---------------- helpers ----------------
__device__ __forceinline__ float4 f4add(float4 a, float4 b) {
    return make_float4(a.x + b.x, a.y + b.y, a.z + b.z, a.w + b.w);
}
__device__ __forceinline__ float4 f4fma(float4 a, float4 b, float4 c) {
    return make_float4(a.x * b.x + c.x, a.y * b.y + c.y, a.z * b.z + c.z, a.w * b.w + c.w);
}
__device__ __forceinline__ float4 f4smad(float s, float4 a, float4 acc) {
    return make_float4(s * a.x + acc.x, s * a.y + acc.y, s * a.z + acc.z, s * a.w + acc.w);
}
__device__ __forceinline__ float4 f4rsub1(float4 a) {
    return make_float4(1.f - a.x, 1.f - a.y, 1.f - a.z, 1.f - a.w);
}
__device__ __forceinline__ float ftanh(float x) {   // 1 - 2/(1+e^{2x}); ~2ulp via __expf
    return 1.f - 2.f / (1.f + __expf(2.f * x));
}
__device__ __forceinline__ float fsig(float x) {
    return 1.f / (1.f + __expf(-x));
}
__device__ __forceinline__ float4 f4tanh(float4 a) {
    return make_float4(ftanh(a.x), ftanh(a.y), ftanh(a.z), ftanh(a.w));
}
__device__ __forceinline__ float4 f4sig(float4 a) {
    return make_float4(fsig(a.x), fsig(a.y), fsig(a.z), fsig(a.w));
}
__device__ __forceinline__ float dot4(float4 a, float4 b) {
    return a.x * b.x + a.y * b.y + a.z * b.z + a.w * b.w;
}
__device__ __forceinline__ float4 ld4(const float* p, int i) {
    return __ldg(((const float4*)p) + i);
}
__device__ __forceinline__ float wred(float v) {
    v += __shfl_down_sync(0xffffffffu, v, 16);
    v += __shfl_down_sync(0xffffffffu, v, 8);
    v += __shfl_down_sync(0xffffffffu, v, 4);
    v += __shfl_down_sync(0xffffffffu, v, 2);
    v += __shfl_down_sync(0xffffffffu, v, 1);
    return v;
}

// Candidate values for the score_mix fused into stage MODE (2,3,4).
template<int MODE>
__device__ __forceinline__ void cands(const P& p, int idx, int l, float4* cc) {
    float4 b_ = ld4(p.b + l * H, idx);
    if (MODE == 2) {
        if (l < 3) {
            float4 hl = ld4(p.hL + l * H, idx);
            float4 rr = ld4(p.Rr + l * H, idx);
            float4 rz = ld4(p.Rz1 + l * H, idx);
            cc[0] = f4fma(hl, rr, b_);
            cc[1] = f4rsub1(f4add(rz, b_));
            cc[2] = f4fma(hl, rz, b_);
        } else {
            float4 hp4 = ld4(p.hp, idx);
            float4 r4  = ld4(p.r, idx);
            float4 z4  = ld4(p.z1, idx);
            cc[0] = f4fma(hp4, r4, b_);
            cc[1] = f4rsub1(f4add(z4, b_));
            cc[2] = f4fma(hp4, z4, b_);
        }
    } else if (MODE == 3) {
        if (l < 3)
            cc[0] = f4tanh(f4add(f4add(ld4(p.xL + l * H, idx), ld4(p.Rrh + l * H, idx)), b_));
        else
            cc[0] = f4tanh(f4add(f4add(ld4(p.x, idx), ld4(p.rh, idx)), b_));
    } else {  // MODE == 4
        if (l < 3)
            cc[0] = f4fma(ld4(p.Lht + l * H, idx), ld4(p.RoneMZ + l * H, idx), b_);
        else
            cc[0] = f4fma(ld4(p.htilde, idx), ld4(p.oneMZ, idx), b_);
    }
}

// ---------------------------------------------------------------------------
// Fused kernel: [score_mix / glue prologue -> smem v] + streaming matvec.
// Block (8,64) = 512 threads: tx -> 4 cols (float4), ty -> 64-row h-slice.
// Tiles are 32 columns -> 128 tiles per (W,l) unit.
// MODE 0: stage A  grid 640 (L x {x,hp} l=0..2 ; R x {hp} l=0..1)
// MODE 1: stage B  grid 384 (sigmoid glue; R x {r,z1})
// MODE 2: stage C  grid 384 (3-way score_mix; R x {rh,oneMZ,z2h})
// MODE 3: stage D  grid 384 (h_tilde mix; L x {htilde})
// MODE 4: stage E  grid 384 (zh_tilde mix; L x {zhtil})
// Every block spans all h -> computes mix weights redundantly (identical).
// Mainloop reduction buffer ALIASES dynamic smem (vsm dead by then).
// ---------------------------------------------------------------------------
template<int MODE>
__global__ void __launch_bounds__(512, 2) fused_kernel(P p) {
    extern __shared__ float vsm[];                 // [NV][H] mixture/v vectors
    __shared__ float red[12][16];
    __shared__ float wsm[3][4];

    constexpr int NVMAX = (MODE == 2) ? 3 : ((MODE <= 1) ? 2 : 1);

    const int tx = threadIdx.x, ty = threadIdx.y;  // 8 x 64
    const int t = ty * 8 + tx;
    const int lane = t & 31, warp = t >> 5;
    const int bx = blockIdx.x;

    // decode work unit
    int l, kb, nv;
    const float* W;
    float *y0 = nullptr, *y1 = nullptr, *y2 = nullptr;
    if (MODE == 0) {
        const int unit = bx >> 7; kb = bx & 127;
        if (unit < 3) { W = p.L; l = unit;     nv = 2; y0 = p.xL; y1 = p.hL; }
        else          { W = p.R; l = unit - 3; nv = 1; y0 = p.hR; }
    } else {
        l = bx >> 7; kb = bx & 127;
        nv = NVMAX;
        if (MODE == 1) { y0 = p.Rr;  y1 = p.Rz1; W = p.R; }
        if (MODE == 2) { y0 = p.Rrh; y1 = p.RoneMZ; y2 = p.Rz2h; W = p.R; }
        if (MODE == 3) { y0 = p.Lht; W = p.L; }
        if (MODE == 4) { y0 = p.Lzh; W = p.L; }
    }

    // ---------------- prologue: fill vsm ----------------
    if (MODE == 0) {
        const int unit = bx >> 7;
        #pragma unroll
        for (int c = 0; c < 2; ++c) {
            int idx = t + c * 512;
            if (unit < 3) {
                ((float4*)vsm)[idx]       = ld4(p.x, idx);
                ((float4*)(vsm + H))[idx] = ld4(p.hp, idx);
            } else {
                ((float4*)vsm)[idx] = ld4(p.hp, idx);
            }
        }
        __syncthreads();
    } else if (MODE == 1) {
        #pragma unroll
        for (int c = 0; c < 2; ++c) {
            int idx = t + c * 512;
            float4 z14 = f4sig(f4add(f4add(ld4(p.xL, idx),     ld4(p.hR, idx)),     ld4(p.b, idx)));
            float4 r4  = f4sig(f4add(f4add(ld4(p.xL + H, idx), ld4(p.hR + H, idx)), ld4(p.b + H, idx)));
            ((float4*)vsm)[idx]       = r4;    // v0 = r
            ((float4*)(vsm + H))[idx] = z14;   // v1 = z1
            if (bx == 0) {
                ((float4*)p.r)[idx]  = r4;
                ((float4*)p.z1)[idx] = z14;
            }
        }
        if (bx == 0 && t < 3) p.out[4096 + t] = (t == 1) ? 1.f : 0.f;
        __syncthreads();
    } else {
        constexpr int NM = (MODE == 2) ? 3 : 1;
        float s[NM * 4];
        #pragma unroll
        for (int d = 0; d < NM * 4; ++d) s[d] = 0.f;

        #pragma unroll
        for (int c = 0; c < 2; ++c) {
            int idx = t + c * 512;
            float4 ws = ld4(p.Wsc, idx);
            #pragma unroll
            for (int ll = 0; ll < 4; ++ll) {
                float4 cc[NM];
                cands<MODE>(p, idx, ll, cc);
                #pragma unroll
                for (int m = 0; m < NM; ++m) s[m * 4 + ll] += dot4(cc[m], ws);
            }
        }
        #pragma unroll
        for (int d = 0; d < NM * 4; ++d) {
            float v = wred(s[d]);
            if (lane == 0) red[d][warp] = v;
        }
        __syncthreads();
        if (t == 0) {
            #pragma unroll
            for (int m = 0; m < NM; ++m) {
                float sc[4];
                #pragma unroll
                for (int l2 = 0; l2 < 4; ++l2) {
                    float a = 0.f;
                    #pragma unroll
                    for (int w2 = 0; w2 < 16; ++w2) a += red[m * 4 + l2][w2];
                    sc[l2] = a;
                }
                int amax = 0; float m1 = sc[0];
                for (int l2 = 1; l2 < 4; ++l2) if (sc[l2] > m1) { m1 = sc[l2]; amax = l2; }
                float m2 = -INFINITY;
                for (int l2 = 0; l2 < 4; ++l2) if (l2 != amax && sc[l2] > m2) m2 = sc[l2];
                float e[4], se = 0.f;
                for (int l2 = 0; l2 < 4; ++l2) { e[l2] = __expf(sc[l2] - m1); se += e[l2]; }
                for (int l2 = 0; l2 < 4; ++l2) wsm[m][l2] = e[l2] / se;
                if (bx == 0) {
                    int slot = (MODE == 2) ? (m * 2) : ((MODE == 3) ? 1 : 3);
                    p.out[4096 + 3 + slot] = (float)amax;
                    p.out[4096 + 9 + slot] = m1 - m2;
                }
            }
        }
        __syncthreads();

        float* gv[NM];
        if (MODE == 2) { gv[0] = p.rh; gv[1] = p.oneMZ; gv[2] = p.z2h; }
        if (MODE == 3) { gv[0] = p.htilde; }
        if (MODE == 4) { gv[0] = p.zhtil; }

        #pragma unroll
        for (int c = 0; c < 2; ++c) {
            int idx = t + c * 512;
            float4 v[NM];
            #pragma unroll
            for (int m = 0; m < NM; ++m) v[m] = make_float4(0.f, 0.f, 0.f, 0.f);
            #pragma unroll
            for (int ll = 0; ll < 4; ++ll) {
                float4 cc[NM];
                cands<MODE>(p, idx, ll, cc);
                #pragma unroll
                for (int m = 0; m < NM; ++m) v[m] = f4smad(wsm[m][ll], cc[m], v[m]);
            }
            #pragma unroll
            for (int m = 0; m < NM; ++m) {
                ((float4*)(vsm + m * H))[idx] = v[m];
                if (bx == 0) ((float4*)gv[m])[idx] = v[m];
            }
        }
        __syncthreads();
    }

    // ---------------- streaming matvec mainloop ----------------
    const int k0 = (kb << 5) + (tx << 2);     // 32-col tile
    const int h0 = ty << 6;                    // 64 rows per ty slice
    const float* __restrict__ Wp = W + (size_t)l * H * H + (size_t)h0 * H + k0;
    float4 a0 = make_float4(0.f, 0.f, 0.f, 0.f);
    float4 a1 = a0, a2 = a0;
    const float* v0s = vsm + h0;
    const float* v1s = vsm + H + h0;
    const float* v2s = vsm + 2 * H + h0;

    if (NVMAX == 1 || nv == 1) {
        #pragma unroll 8
        for (int h = 0; h < 64; ++h) {
            float4 w = __ldg((const float4*)(Wp + (size_t)h * H));
            a0 = f4smad(v0s[h], w, a0);
        }
    } else if (NVMAX == 2 || nv == 2) {
        #pragma unroll 4
        for (int h = 0; h < 64; ++h) {
            float4 w = __ldg((const float4*)(Wp + (size_t)h * H));
            float s0 = v0s[h], s1 = v1s[h];
            a0 = f4smad(s0, w, a0);
            a1 = f4smad(s1, w, a1);
        }
    } else {
        #pragma unroll 4
        for (int h = 0; h < 64; ++h) {
            float4 w = __ldg((const float4*)(Wp + (size_t)h * H));
            float s0 = v0s[h], s1 = v1s[h], s2 = v2s[h];
            a0 = f4smad(s0, w, a0);
            a1 = f4smad(s1, w, a1);
            a2 = f4smad(s2, w, a2);
        }
    }

    // vsm is dead; alias reduction buffer. [NVMAX][64][8] float4.
    __syncthreads();
    float4* smred = (float4*)vsm;
    #define SMRED(vv, yy, xx) smred[((vv) * 64 + (yy)) * 8 + (xx)]
    SMRED(0, ty, tx) = a0;
    if (NVMAX > 1 && nv > 1) SMRED(1, ty, tx) = a1;
    if (NVMAX > 2) SMRED(2, ty, tx) = a2;
    __syncthreads();

    #pragma unroll
    for (int s = 32; s > 0; s >>= 1) {
        if (ty < s) {
            #pragma unroll
            for (int vv = 0; vv < NVMAX; ++vv)
                if (vv < nv)
                    SMRED(vv, ty, tx) = f4add(SMRED(vv, ty, tx), SMRED(vv, ty + s, tx));
        }
        __syncthreads();
    }

    if (ty == 0) {
        *(float4*)(y0 + l * H + k0) = SMRED(0, 0, tx);
        if (NVMAX > 1 && nv > 1) *(float4*)(y1 + l * H + k0) = SMRED(1, 0, tx);
        if (NVMAX > 2) *(float4*)(y2 + l * H + k0) = SMRED(2, 0, tx);
    }
    #undef SMRED
}

// ---------------------------------------------------------------------------
// Final score_mix: h_next = mix(Lzh + Rz2h + b), cand3 = zhtil + z2h + b3.
// ---------------------------------------------------------------------------
__global__ void __launch_bounds__(1024) final_kernel(P p) {
    const int t = threadIdx.x;
    const int lane = t & 31, warp = t >> 5;
    __shared__ float red2[4][32];
    __shared__ float wsh[4];

    float4 ws = ld4(p.Wsc, t);
    float4 cc[4];
    #pragma unroll
    for (int l = 0; l < 3; ++l)
        cc[l] = f4add(f4add(ld4(p.Lzh + l * H, t), ld4(p.Rz2h + l * H, t)), ld4(p.b + l * H, t));
    cc[3] = f4add(f4add(ld4(p.zhtil, t), ld4(p.z2h, t)), ld4(p.b + 3 * H, t));

    #pragma unroll
    for (int l = 0; l < 4; ++l) {
        float v = wred(dot4(cc[l], ws));
        if (lane == 0) red2[l][warp] = v;
    }
    __syncthreads();
    if (warp == 0) {
        float v[4];
        #pragma unroll
        for (int l = 0; l < 4; ++l) {
            v[l] = red2[l][lane];
            #pragma unroll
            for (int off = 16; off > 0; off >>= 1)
                v[l] += __shfl_down_sync(0xffffffffu, v[l], off);
        }
        if (lane == 0) {
            int amax = 0; float m1 = v[0];
            for (int l = 1; l < 4; ++l) if (v[l] > m1) { m1 = v[l]; amax = l; }
            float m2 = -INFINITY;
            for (int l = 0; l < 4; ++l) if (l != amax && v[l] > m2) m2 = v[l];
            float e[4], se = 0.f;
            for (int l = 0; l < 4; ++l) { e[l] = __expf(v[l] - m1); se += e[l]; }
            for (int l = 0; l < 4; ++l) wsh[l] = e[l] / se;
            p.out[4096 + 3 + 5] = (float)amax;
            p.out[4096 + 9 + 5] = m1 - m2;
        }
    }
    __syncthreads();

    float4 o = make_float4(0.f, 0.f, 0.f, 0.f);
    #pragma unroll
    for (int l = 0; l < 4; ++l) o = f4smad(wsh[l], cc[l], o);
    ((float4*)p.out)[t] = o;
}

// ---------------------------------------------------------------------------
// Launch sequence (graph-capturable: kernel launches only, default stream).
// ---------------------------------------------------------------------------
extern "C" void kernel_launch(void* const* d_in, const int* in_sizes, int n_in,
                              void* d_out_v, int out_size) {
    float* S = nullptr;
    cudaGetSymbolAddress((void**)&S, g_scratch);

    P p;
    p.L   = (const float*)d_in[2];
    p.R   = (const float*)d_in[3];
    p.x   = (const float*)d_in[0];
    p.hp  = (const float*)d_in[1];
    p.b   = (const float*)d_in[4];
    p.Wsc = (const float*)d_in[5];
    p.out = (float*)d_out_v;

    p.xL     = S + 0 * H;   p.hL     = S + 3 * H;   p.hR     = S + 6 * H;  // hR: 2H
    p.Rr     = S + 8 * H;   p.Rz1    = S + 11 * H;
    p.Rrh    = S + 14 * H;  p.RoneMZ = S + 17 * H;  p.Rz2h   = S + 20 * H;
    p.Lht    = S + 23 * H;  p.Lzh    = S + 26 * H;
    p.r      = S + 29 * H;  p.z1     = S + 30 * H;  p.rh     = S + 31 * H;
    p.oneMZ  = S + 32 * H;  p.z2h    = S + 33 * H;
    p.htilde = S + 34 * H;  p.zhtil  = S + 35 * H;

    const int DSM1 = 1 * H * (int)sizeof(float);   // 16KB
    const int DSM2 = 2 * H * (int)sizeof(float);   // 32KB
    const int DSM3 = 3 * H * (int)sizeof(float);   // 48KB
    cudaFuncSetAttribute(fused_kernel<0>, cudaFuncAttributeMaxDynamicSharedMemorySize, DSM3);
    cudaFuncSetAttribute(fused_kernel<1>, cudaFuncAttributeMaxDynamicSharedMemorySize, DSM3);
    cudaFuncSetAttribute(fused_kernel<2>, cudaFuncAttributeMaxDynamicSharedMemorySize, DSM3);
    cudaFuncSetAttribute(fused_kernel<3>, cudaFuncAttributeMaxDynamicSharedMemorySize, DSM3);
    cudaFuncSetAttribute(fused_kernel<4>, cudaFuncAttributeMaxDynamicSharedMemorySize, DSM3);

    dim3 blk(8, 64);

    fused_kernel<0><<<640, blk, DSM2>>>(p);  // A: L x {x,hp}, R x {hp}      320MB
    fused_kernel<1><<<384, blk, DSM2>>>(p);  // B: glue + R x {r,z1}         192MB
    fused_kernel<2><<<384, blk, DSM3>>>(p);  // C: 3-mix + R x {rh,oMZ,z2h}  192MB
    fused_kernel<3><<<384, blk, DSM1>>>(p);  // D: h_tilde + L x {htilde}    192MB
    fused_kernel<4><<<384, blk, DSM1>>>(p);  // E: zh_tilde + L x {zhtil}    192MB
    final_kernel<<<1, 1024>>>(p);            // F: h_next
}